// round 1
// baseline (speedup 1.0000x reference)
#include <cuda_runtime.h>
#include <math.h>

// Analytic factorization of the pairwise-exp kernel:
//   e^{u.v} = sum_{a+b+c<=K} (1/(a!b!c!)) u^(a,b,c) v^(a,b,c)   (|u.v| <= 1)
// K=10 -> 286 features, truncation error < 2.6e-8 per pair term.
// Z_i = sum_j e^{s_ij} = sum_f c_f * mono_f(u_i) * M_f
// W_i = sum_j s_ij e^{s_ij} = sum_f (|f| c_f) * mono_f(u_i) * M_f
// H_i = log Z_i - W_i/Z_i - N*1e-8   (log(p+eps) first-order; 2nd order ~2e-8)

#define KDEG  10
#define NFEAT 286            // C(13,3)
#define TPB   256
#define MAXBLK 256

__device__ float g_Mp[MAXBLK * NFEAT];   // per-block moment partials
__device__ float g_Hp[MAXBLK];           // per-block entropy partials

__device__ __forceinline__ void load_unit(const float* __restrict__ vel, int i,
                                          float& x, float& y, float& z) {
    x = vel[3 * i + 0];
    y = vel[3 * i + 1];
    z = vel[3 * i + 2];
    float nrm = sqrtf(x * x + y * y + z * z);
    float inv = 1.0f / (nrm + 1e-6f);
    x *= inv; y *= inv; z *= inv;
}

// ---------------- Kernel 1: per-block moments M_f = sum_j u_j^f ----------------
__global__ void __launch_bounds__(TPB)
moments_kernel(const float* __restrict__ vel, int N) {
    __shared__ float s[NFEAT * 8];   // [feat][warp]
    int tid  = threadIdx.x;
    int lane = tid & 31;
    int warp = tid >> 5;

    int i = blockIdx.x * TPB + tid;
    float x = 0.f, y = 0.f, z = 0.f, w = 0.f;
    if (i < N) {
        load_unit(vel, i, x, y, z);
        w = 1.0f;
    }

    // power tables; px[0]=w masks out-of-range threads from ALL monomials
    float px[KDEG + 1], py[KDEG + 1], pz[KDEG + 1];
    px[0] = w; py[0] = 1.0f; pz[0] = 1.0f;
#pragma unroll
    for (int d = 1; d <= KDEG; d++) {
        px[d] = px[d - 1] * x;
        py[d] = py[d - 1] * y;
        pz[d] = pz[d - 1] * z;
    }

    int idx = 0;
#pragma unroll
    for (int a = 0; a <= KDEG; a++) {
#pragma unroll
        for (int b = 0; b <= KDEG - a; b++) {
            float xy = px[a] * py[b];
#pragma unroll
            for (int c = 0; c <= KDEG - a - b; c++) {
                float m = xy * pz[c];
                m += __shfl_xor_sync(0xffffffffu, m, 16);
                m += __shfl_xor_sync(0xffffffffu, m, 8);
                m += __shfl_xor_sync(0xffffffffu, m, 4);
                m += __shfl_xor_sync(0xffffffffu, m, 2);
                m += __shfl_xor_sync(0xffffffffu, m, 1);
                if (lane == 0) s[idx * 8 + warp] = m;
                idx++;
            }
        }
    }
    __syncthreads();

    for (int f = tid; f < NFEAT; f += TPB) {
        float acc = 0.f;
#pragma unroll
        for (int wi = 0; wi < 8; wi++) acc += s[f * 8 + wi];
        g_Mp[blockIdx.x * NFEAT + f] = acc;
    }
}

// ---------------- Kernel 2: per-point entropy, per-block sums ----------------
__global__ void __launch_bounds__(TPB)
entropy_kernel(const float* __restrict__ vel, int N, int nblk) {
    __shared__ float sM[NFEAT];
    __shared__ float red[TPB];
    int tid = threadIdx.x;

    // reduce block partials into full moments (redundantly per block; L2-cached)
    for (int f = tid; f < NFEAT; f += TPB) {
        float acc = 0.f;
        for (int b = 0; b < nblk; b++) acc += g_Mp[b * NFEAT + f];
        sM[f] = acc;
    }
    __syncthreads();

    const float INVF[KDEG + 1] = {
        1.0f, 1.0f, 0.5f, 1.0f / 6.0f, 1.0f / 24.0f, 1.0f / 120.0f,
        1.0f / 720.0f, 1.0f / 5040.0f, 1.0f / 40320.0f,
        1.0f / 362880.0f, 1.0f / 3628800.0f
    };

    int i = blockIdx.x * TPB + tid;
    float H = 0.f;
    if (i < N) {
        float x, y, z;
        load_unit(vel, i, x, y, z);

        float px[KDEG + 1], py[KDEG + 1], pz[KDEG + 1];
        px[0] = 1.0f; py[0] = 1.0f; pz[0] = 1.0f;
#pragma unroll
        for (int d = 1; d <= KDEG; d++) {
            px[d] = px[d - 1] * x;
            py[d] = py[d - 1] * y;
            pz[d] = pz[d - 1] * z;
        }

        float Z = 0.f, W = 0.f;
        int idx = 0;
#pragma unroll
        for (int a = 0; a <= KDEG; a++) {
#pragma unroll
            for (int b = 0; b <= KDEG - a; b++) {
                float xy = px[a] * py[b];
#pragma unroll
                for (int c = 0; c <= KDEG - a - b; c++) {
                    float mono = xy * pz[c];
                    float t = mono * sM[idx];
                    float cf = INVF[a] * INVF[b] * INVF[c];      // compile-time imm
                    Z = fmaf(cf, t, Z);
                    W = fmaf(cf * (float)(a + b + c), t, W);     // compile-time imm
                    idx++;
                }
            }
        }
        H = logf(Z) - W / Z - (float)N * 1e-8f;
    }

    red[tid] = H;
    __syncthreads();
#pragma unroll
    for (int stride = TPB / 2; stride > 0; stride >>= 1) {
        if (tid < stride) red[tid] += red[tid + stride];
        __syncthreads();
    }
    if (tid == 0) g_Hp[blockIdx.x] = red[0];
}

// ---------------- Kernel 3: finalize mean ----------------
__global__ void finalize_kernel(float* __restrict__ out, int N, int nblk) {
    float acc = 0.f;
    for (int b = threadIdx.x; b < nblk; b += 32) acc += g_Hp[b];
    acc += __shfl_xor_sync(0xffffffffu, acc, 16);
    acc += __shfl_xor_sync(0xffffffffu, acc, 8);
    acc += __shfl_xor_sync(0xffffffffu, acc, 4);
    acc += __shfl_xor_sync(0xffffffffu, acc, 2);
    acc += __shfl_xor_sync(0xffffffffu, acc, 1);
    if (threadIdx.x == 0) out[0] = acc / (float)N;
}

extern "C" void kernel_launch(void* const* d_in, const int* in_sizes, int n_in,
                              void* d_out, int out_size) {
    const float* vel = (const float*)d_in[0];   // velocities (N,3); positions unused
    int N = in_sizes[0] / 3;
    int nblk = (N + TPB - 1) / TPB;
    if (nblk > MAXBLK) nblk = MAXBLK;           // N<=65536 by construction (N=16384)

    moments_kernel<<<nblk, TPB>>>(vel, N);
    entropy_kernel<<<nblk, TPB>>>(vel, N, nblk);
    finalize_kernel<<<1, 32>>>((float*)d_out, N, nblk);
}

// round 2
// speedup vs baseline: 1.7413x; 1.7413x over previous
#include <cuda_runtime.h>
#include <math.h>

// e^{u.v} = sum_{a+b+c<=10} u^(a,b,c) v^(a,b,c) / (a!b!c!)   (|u.v|<=1, trunc err <3e-8)
// Z_i = sum_f c_f mono_f(u_i) M_f,  W_i = sum_f |f| c_f mono_f(u_i) M_f,  M_f = sum_j mono_f(u_j)
// H_i = log Z_i - W_i/Z_i - N*1e-8

#define KDEG   10
#define NF     286
#define NFP    288          // padded to 9*32
#define NGRP   9
#define TPB    128
#define MAXBLK 512

__device__ float  g_Mp[MAXBLK * NFP];   // per-block raw moment partials [blk][feat]
__device__ float2 g_MZW[NFP];           // (c_f*M_f, |f|*c_f*M_f)
__device__ float  g_Hp[MAXBLK];

__device__ __forceinline__ void load_unit(const float* __restrict__ vel, int i,
                                          float& x, float& y, float& z) {
    x = vel[3 * i + 0];
    y = vel[3 * i + 1];
    z = vel[3 * i + 2];
    float nrm = sqrtf(x * x + y * y + z * z);
    float inv = 1.0f / (nrm + 1e-6f);
    x *= inv; y *= inv; z *= inv;
}

// Butterfly compaction: 32 values across 32 lanes -> lane l holds full-warp sum
// of value index l. 31 shuffles total (vs 160 for 32x tree reduce).
__device__ __forceinline__ float bfly32(float (&v)[32], int lane) {
#pragma unroll
    for (int m = 16; m >= 1; m >>= 1) {
        bool hi = (lane & m) != 0;
#pragma unroll
        for (int k = 0; k < 16; k++) {
            if (k < m) {
                float keep = hi ? v[k + m] : v[k];
                float send = hi ? v[k] : v[k + m];
                v[k] = keep + __shfl_xor_sync(0xffffffffu, send, m);
            }
        }
    }
    return v[0];
}

// ---------------- K1: raw moments, one point per thread ----------------
__global__ void __launch_bounds__(TPB)
moments_kernel(const float* __restrict__ vel, int N) {
    int tid  = threadIdx.x;
    int lane = tid & 31;
    int warp = tid >> 5;

    int i = blockIdx.x * TPB + tid;
    float x = 0.f, y = 0.f, z = 0.f, w = 0.f;
    if (i < N) { load_unit(vel, i, x, y, z); w = 1.0f; }

    float px[KDEG + 1], py[KDEG + 1], pz[KDEG + 1];
    px[0] = w; py[0] = 1.0f; pz[0] = 1.0f;   // px[0]=w masks inactive threads
#pragma unroll
    for (int d = 1; d <= KDEG; d++) {
        px[d] = px[d - 1] * x;
        py[d] = py[d - 1] * y;
        pz[d] = pz[d - 1] * z;
    }

    float v[32];
    float acc[NGRP];
    int idx = 0;
#pragma unroll
    for (int a = 0; a <= KDEG; a++) {
#pragma unroll
        for (int b = 0; b <= KDEG - a; b++) {
            float xy = px[a] * py[b];
#pragma unroll
            for (int c = 0; c <= KDEG - a - b; c++) {
                v[idx & 31] = xy * pz[c];
                if ((idx & 31) == 31) acc[idx >> 5] = bfly32(v, lane);
                idx++;
            }
        }
    }
    // idx == 286: pad last group
    v[30] = 0.f; v[31] = 0.f;
    acc[8] = bfly32(v, lane);

    __shared__ float s[4][NFP];
#pragma unroll
    for (int g = 0; g < NGRP; g++) s[warp][g * 32 + lane] = acc[g];
    __syncthreads();

    for (int f = tid; f < NFP; f += TPB)
        g_Mp[blockIdx.x * NFP + f] = s[0][f] + s[1][f] + s[2][f] + s[3][f];
}

// ---------------- K2: reduce partials, fold coefficients ----------------
// one warp per feature; 288 warps = 36 blocks x 256 threads
__global__ void __launch_bounds__(256)
reduce_kernel(int nblk) {
    int gw   = (blockIdx.x * blockDim.x + threadIdx.x) >> 5;  // feature
    int lane = threadIdx.x & 31;
    if (gw >= NFP) return;

    float acc = 0.f;
    for (int b = lane; b < nblk; b += 32) acc += g_Mp[b * NFP + gw];
    acc += __shfl_xor_sync(0xffffffffu, acc, 16);
    acc += __shfl_xor_sync(0xffffffffu, acc, 8);
    acc += __shfl_xor_sync(0xffffffffu, acc, 4);
    acc += __shfl_xor_sync(0xffffffffu, acc, 2);
    acc += __shfl_xor_sync(0xffffffffu, acc, 1);

    if (lane == 0) {
        float cf = 0.f, deg = 0.f;
        if (gw < NF) {
            int rem = gw, a = 0, b = 0;
            for (a = 0; a <= KDEG; a++) {
                int cnt = (KDEG + 1 - a) * (KDEG + 2 - a) / 2;
                if (rem < cnt) break;
                rem -= cnt;
            }
            for (b = 0; b <= KDEG - a; b++) {
                int cnt = KDEG + 1 - a - b;
                if (rem < cnt) break;
                rem -= cnt;
            }
            int c = rem;
            float fa = 1.f, fb = 1.f, fc = 1.f;
            for (int t = 2; t <= a; t++) fa *= (float)t;
            for (int t = 2; t <= b; t++) fb *= (float)t;
            for (int t = 2; t <= c; t++) fc *= (float)t;
            cf  = 1.0f / (fa * fb * fc);
            deg = (float)(a + b + c);
        }
        g_MZW[gw] = make_float2(cf * acc, cf * deg * acc);
    }
}

// ---------------- K3: per-point entropy with packed f32x2 FMA ----------------
__global__ void __launch_bounds__(TPB)
entropy_kernel(const float* __restrict__ vel, int N) {
    __shared__ float2 sM[NFP];
    __shared__ float  rs[4];
    int tid  = threadIdx.x;
    int lane = tid & 31;
    int warp = tid >> 5;

    for (int f = tid; f < NFP; f += TPB) sM[f] = g_MZW[f];
    __syncthreads();

    int i = blockIdx.x * TPB + tid;
    float H = 0.f;
    if (i < N) {
        float x, y, z;
        load_unit(vel, i, x, y, z);

        float px[KDEG + 1], py[KDEG + 1], pz[KDEG + 1];
        px[0] = 1.0f; py[0] = 1.0f; pz[0] = 1.0f;
#pragma unroll
        for (int d = 1; d <= KDEG; d++) {
            px[d] = px[d - 1] * x;
            py[d] = py[d - 1] * y;
            pz[d] = pz[d - 1] * z;
        }

        const unsigned long long* sM64 =
            reinterpret_cast<const unsigned long long*>(sM);
        unsigned long long acc2 = 0ull;   // packed (Z, W)
        int idx = 0;
#pragma unroll
        for (int a = 0; a <= KDEG; a++) {
#pragma unroll
            for (int b = 0; b <= KDEG - a; b++) {
                float xy = px[a] * py[b];
#pragma unroll
                for (int c = 0; c <= KDEG - a - b; c++) {
                    float mono = xy * pz[c];
                    unsigned int mu = __float_as_uint(mono);
                    unsigned long long mm, mz;
                    asm("mov.b64 %0, {%1, %1};" : "=l"(mm) : "r"(mu));
                    mz = sM64[idx];
                    asm("fma.rn.f32x2 %0, %1, %2, %3;"
                        : "=l"(acc2) : "l"(mm), "l"(mz), "l"(acc2));
                    idx++;
                }
            }
        }
        unsigned int zu, wu;
        asm("mov.b64 {%0, %1}, %2;" : "=r"(zu), "=r"(wu) : "l"(acc2));
        float Z = __uint_as_float(zu);
        float W = __uint_as_float(wu);
        H = logf(Z) - W / Z - (float)N * 1e-8f;
    }

    // block reduce
    H += __shfl_xor_sync(0xffffffffu, H, 16);
    H += __shfl_xor_sync(0xffffffffu, H, 8);
    H += __shfl_xor_sync(0xffffffffu, H, 4);
    H += __shfl_xor_sync(0xffffffffu, H, 2);
    H += __shfl_xor_sync(0xffffffffu, H, 1);
    if (lane == 0) rs[warp] = H;
    __syncthreads();
    if (tid == 0) g_Hp[blockIdx.x] = rs[0] + rs[1] + rs[2] + rs[3];
}

// ---------------- K4: finalize ----------------
__global__ void finalize_kernel(float* __restrict__ out, int N, int nblk) {
    float acc = 0.f;
    for (int b = threadIdx.x; b < nblk; b += 32) acc += g_Hp[b];
    acc += __shfl_xor_sync(0xffffffffu, acc, 16);
    acc += __shfl_xor_sync(0xffffffffu, acc, 8);
    acc += __shfl_xor_sync(0xffffffffu, acc, 4);
    acc += __shfl_xor_sync(0xffffffffu, acc, 2);
    acc += __shfl_xor_sync(0xffffffffu, acc, 1);
    if (threadIdx.x == 0) out[0] = acc / (float)N;
}

extern "C" void kernel_launch(void* const* d_in, const int* in_sizes, int n_in,
                              void* d_out, int out_size) {
    const float* vel = (const float*)d_in[0];   // velocities (N,3); positions unused
    int N = in_sizes[0] / 3;
    int nblk = (N + TPB - 1) / TPB;
    if (nblk > MAXBLK) nblk = MAXBLK;           // N = 16384 in this problem

    moments_kernel<<<nblk, TPB>>>(vel, N);
    reduce_kernel<<<(NFP * 32 + 255) / 256, 256>>>(nblk);
    entropy_kernel<<<nblk, TPB>>>(vel, N);
    finalize_kernel<<<1, 32>>>((float*)d_out, N, nblk);
}